// round 8
// baseline (speedup 1.0000x reference)
#include <cuda_runtime.h>
#include <cuda_fp16.h>
#include <math.h>
#include <cstdint>

// Problem dims (fixed per reference)
#define Bz 64
#define Tz 512
#define Dz 2048
#define Hz 512
#define BT (Bz * Tz)          // 32768
#define NBLK 4                // H/128 h-blocks for partial scores

// Row partition: 205 CTAs per h-block; each CTA = 128 HMMA rows + 32 fma rows
#define RH 205                // HMMA row-blocks
#define POOL0 (RH * 128)      // 26240: first fma-pool row
#define POOLPC 32             // pool rows per CTA

// Scratch (__device__ globals; allocation-free rule)
__device__ float g_uh[Bz * Hz];
__device__ float g_partial[NBLK * BT];
__device__ float g_att[BT];
__device__ __half g_WaT[Hz * Dz];   // Wa transposed -> [H, D] fp16
__device__ float g_wpart[4 * Bz * Dz];

// ---------------------------------------------------------------------------
// helpers
// ---------------------------------------------------------------------------
__device__ __forceinline__ uint32_t smem_u32(const void* p) {
    uint32_t a;
    asm("{ .reg .u64 t; cvta.to.shared.u64 t, %1; cvt.u32.u64 %0, t; }"
        : "=r"(a) : "l"(p));
    return a;
}

#define SWZ(o) ((o) ^ (((o) >> 3) & 0x70))

__device__ __forceinline__ void ldsm4(uint32_t* a, uint32_t addr) {
    asm volatile("ldmatrix.sync.aligned.m8n8.x4.shared.b16 {%0,%1,%2,%3}, [%4];"
                 : "=r"(a[0]), "=r"(a[1]), "=r"(a[2]), "=r"(a[3]) : "r"(addr));
}
__device__ __forceinline__ uint4 lds128(uint32_t addr) {
    uint4 v;
    asm volatile("ld.shared.v4.u32 {%0,%1,%2,%3}, [%4];"
                 : "=r"(v.x), "=r"(v.y), "=r"(v.z), "=r"(v.w) : "r"(addr));
    return v;
}
// fp16 inputs, fp32 accumulate
__device__ __forceinline__ void mma16816(float* c, const uint32_t* a,
                                         const uint32_t* b) {
    asm volatile(
        "mma.sync.aligned.m16n8k16.row.col.f32.f16.f16.f32 "
        "{%0,%1,%2,%3}, {%4,%5,%6,%7}, {%8,%9}, {%0,%1,%2,%3};"
        : "+f"(c[0]), "+f"(c[1]), "+f"(c[2]), "+f"(c[3])
        : "r"(a[0]), "r"(a[1]), "r"(a[2]), "r"(a[3]), "r"(b[0]), "r"(b[1]));
}
__device__ __forceinline__ uint32_t hfma2u(uint32_t a, uint32_t b, uint32_t c) {
    __half2 r = __hfma2(*(__half2*)&a, *(__half2*)&b, *(__half2*)&c);
    return *(uint32_t*)&r;
}
__device__ __forceinline__ float tanh_fast(float x) {
    float y;
    asm("tanh.approx.f32 %0, %1;" : "=f"(y) : "f"(x));
    return y;
}

// ---------------------------------------------------------------------------
// Kernel 0: WaT[n][k] = fp16(Wa[k][n])
// ---------------------------------------------------------------------------
__global__ void transpose_kernel(const float* __restrict__ Wa,
                                 __half* __restrict__ WaT) {
    __shared__ float tile[32][33];
    const int k0 = blockIdx.x * 32, n0 = blockIdx.y * 32;
    for (int i = threadIdx.y; i < 32; i += 8)
        tile[i][threadIdx.x] = Wa[(size_t)(k0 + i) * Hz + n0 + threadIdx.x];
    __syncthreads();
    for (int i = threadIdx.y; i < 32; i += 8)
        WaT[(size_t)(n0 + i) * Dz + k0 + threadIdx.x] =
            __float2half_rn(tile[threadIdx.x][i]);
}

// ---------------------------------------------------------------------------
// Kernel 1: Uh[b,h] = sum_d text[b,d] * Ua[d,h] + ba[h]   (fp32)
// ---------------------------------------------------------------------------
__global__ void uh_kernel(const float* __restrict__ text,
                          const float* __restrict__ Ua,
                          const float* __restrict__ ba,
                          float* __restrict__ uh) {
    const int h  = blockIdx.x * 128 + threadIdx.x;
    const int b0 = blockIdx.y * 8;
    float acc[8] = {0.f, 0.f, 0.f, 0.f, 0.f, 0.f, 0.f, 0.f};
    __shared__ float ts[8][32];

    for (int d0 = 0; d0 < Dz; d0 += 32) {
        for (int v = threadIdx.x; v < 8 * 32; v += 128) {
            int i = v >> 5, k = v & 31;
            ts[i][k] = text[(b0 + i) * Dz + d0 + k];
        }
        __syncthreads();
        #pragma unroll
        for (int k = 0; k < 32; k++) {
            float u = Ua[(size_t)(d0 + k) * Hz + h];
            #pragma unroll
            for (int i = 0; i < 8; i++) acc[i] = fmaf(ts[i][k], u, acc[i]);
        }
        __syncthreads();
    }
    float bav = ba[h];
    #pragma unroll
    for (int i = 0; i < 8; i++) uh[(b0 + i) * Hz + h] = acc[i] + bav;
}

// ---------------------------------------------------------------------------
// Kernel 2: hybrid tensor+fma score GEMM, fused tanh·Va epilogue.
// 384 threads = 12 warps:
//   warps 0-7 : HMMA fp16->fp32, 128 rows x 128 h (R4 pipeline)
//   warps 8-11: HFMA2 fp16 GEMM, 32 pool rows x 128 h (fma pipe)
// K=2048 in 32 chunks of 64; triple-buffered smem, one sync per chunk.
// ---------------------------------------------------------------------------
#define ABUF(s) ((uint32_t)(s) * 16384u)            // A: 3 x 16KB
#define BBUF(s) (49152u + (uint32_t)(s) * 16384u)   // B: 3 x 16KB
#define FBUF(s) (98304u + (uint32_t)(s) * 4096u)    // Af: 3 x 4KB
#define SM_TOTAL 110592
#define NCHUNK 32

__global__ __launch_bounds__(384, 1)
void score_hmma_kernel(const float* __restrict__ frames,
                       const __half* __restrict__ WaT,
                       const float* __restrict__ uh,
                       const float* __restrict__ Va,
                       float* __restrict__ partial) {
    extern __shared__ char smem[];
    const uint32_t sbase = smem_u32(smem);
    const int tid = threadIdx.x;
    const int wid = tid >> 5, lane = tid & 31;
    const int h0   = blockIdx.x * 128;
    const int row0 = blockIdx.y * 128;               // HMMA rows
    const int pool0 = POOL0 + blockIdx.y * POOLPC;   // fma rows
    const bool valid = pool0 < BT;

    // HMMA role params (warps 0-7 as 2M x 4N, warp tile 64x32)
    const int warp_m = wid & 1, warp_n = (wid >> 1) & 3;
    const int wm = warp_m * 64, wn = warp_n * 32;

    // fma role params (warps 8-11, 8 rows each; lane = tr*8 + tc)
    const int tr = lane >> 3, tc = lane & 7;
    const int rt0 = (wid - 8) * 8 + tr * 2;          // row-in-pool-tile
    const int ft = tid - 256;                        // 0..127 for fma threads

    float acc[4][4][4];
    #pragma unroll
    for (int i = 0; i < 4; i++)
        #pragma unroll
        for (int j = 0; j < 4; j++)
            #pragma unroll
            for (int e = 0; e < 4; e++) acc[i][j][e] = 0.f;

    float facc[2][16];
    #pragma unroll
    for (int r = 0; r < 2; r++)
        #pragma unroll
        for (int j = 0; j < 16; j++) facc[r][j] = 0.f;

    float4 pa[8], pb[4], pf[4];

    // ---- HMMA loaders (threads 0-255) ----
    auto loadG = [&](int c) {
        const float* fA = frames + (size_t)row0 * Dz + c * 64;
        #pragma unroll
        for (int v = 0; v < 8; v++) {
            int idx = tid + v * 256;
            int r = idx >> 4, c4 = (idx & 15) << 2;
            pa[v] = *(const float4*)(fA + (size_t)r * Dz + c4);
        }
        const __half* fB = WaT + (size_t)h0 * Dz + c * 64;
        #pragma unroll
        for (int v = 0; v < 4; v++) {
            int idx = tid + v * 256;
            int n = idx >> 3, k8 = (idx & 7) << 3;
            pb[v] = *(const float4*)(fB + (size_t)n * Dz + k8);
        }
    };
    auto storeS = [&](int s) {
        const uint32_t aoff = ABUF(s), boff = BBUF(s);
        #pragma unroll
        for (int v = 0; v < 8; v++) {
            int idx = tid + v * 256;
            int r = idx >> 4, c4 = (idx & 15) << 2;
            __half2 p0 = __float22half2_rn(make_float2(pa[v].x, pa[v].y));
            __half2 p1 = __float22half2_rn(make_float2(pa[v].z, pa[v].w));
            uint2 pk;
            pk.x = *(uint32_t*)&p0;
            pk.y = *(uint32_t*)&p1;
            *(uint2*)(smem + aoff + SWZ((uint32_t)(r * 128 + c4 * 2))) = pk;
        }
        #pragma unroll
        for (int v = 0; v < 4; v++) {
            int idx = tid + v * 256;
            int n = idx >> 3, k8 = (idx & 7) << 3;
            *(float4*)(smem + boff + SWZ((uint32_t)(n * 128 + k8 * 2))) = pb[v];
        }
    };
    // ---- fma loaders (threads 256-383) ----
    auto loadGf = [&](int c) {
        const float* fA = frames + (size_t)pool0 * Dz + c * 64;
        #pragma unroll
        for (int v = 0; v < 4; v++) {
            int idx = ft + v * 128;          // 32 rows x 16 float4
            int r = idx >> 4, c4 = (idx & 15) << 2;
            pf[v] = *(const float4*)(fA + (size_t)r * Dz + c4);
        }
    };
    auto storeSf = [&](int s) {
        const uint32_t foff = FBUF(s);
        #pragma unroll
        for (int v = 0; v < 4; v++) {
            int idx = ft + v * 128;
            int r = idx >> 4, c4 = (idx & 15) << 2;
            __half2 p0 = __float22half2_rn(make_float2(pf[v].x, pf[v].y));
            __half2 p1 = __float22half2_rn(make_float2(pf[v].z, pf[v].w));
            uint2 pk;
            pk.x = *(uint32_t*)&p0;
            pk.y = *(uint32_t*)&p1;
            *(uint2*)(smem + foff + SWZ((uint32_t)(r * 128 + c4 * 2))) = pk;
        }
    };

    // ---- HMMA compute: 4 k16-steps, warp tile 64x32 ----
    auto compute = [&](int s) {
        const uint32_t aoff = ABUF(s), boff = BBUF(s);
        #pragma unroll
        for (int ks = 0; ks < 4; ks++) {
            const int k16 = ks * 16;
            uint32_t bfr[4][2];
            #pragma unroll
            for (int jj = 0; jj < 2; jj++) {
                uint32_t r4[4];
                int g = lane >> 3;
                uint32_t off = (uint32_t)((wn + jj * 16 + (g >> 1) * 8 + (lane & 7)) * 128 +
                                          (k16 + (g & 1) * 8) * 2);
                ldsm4(r4, sbase + boff + SWZ(off));
                bfr[jj * 2 + 0][0] = r4[0]; bfr[jj * 2 + 0][1] = r4[1];
                bfr[jj * 2 + 1][0] = r4[2]; bfr[jj * 2 + 1][1] = r4[3];
            }
            #pragma unroll
            for (int i = 0; i < 4; i++) {
                uint32_t afr[4];
                uint32_t off = (uint32_t)((wm + i * 16 + (lane & 15)) * 128 +
                                          (k16 + (lane >> 4) * 8) * 2);
                ldsm4(afr, sbase + aoff + SWZ(off));
                #pragma unroll
                for (int j = 0; j < 4; j++)
                    mma16816(acc[i][j], afr, bfr[j]);
            }
        }
    };
    // ---- fma compute: HFMA2 over chunk, fp16 chunk-acc -> fp32 ----
    auto fcompute = [&](int s) {
        const uint32_t foff = FBUF(s), boff = BBUF(s);
        #pragma unroll
        for (int jh = 0; jh < 2; jh++) {
            uint32_t hacc[2][8];
            #pragma unroll
            for (int r = 0; r < 2; r++)
                #pragma unroll
                for (int j = 0; j < 8; j++) hacc[r][j] = 0u;
            #pragma unroll
            for (int kb = 0; kb < 8; kb++) {
                uint4 a0 = lds128(sbase + foff + SWZ((uint32_t)(rt0 * 128 + kb * 16)));
                uint4 a1 = lds128(sbase + foff + SWZ((uint32_t)((rt0 + 1) * 128 + kb * 16)));
                #pragma unroll
                for (int j = 0; j < 8; j++) {
                    int c = (jh * 8 + j) * 8 + tc;
                    uint4 bb = lds128(sbase + boff + SWZ((uint32_t)(c * 128 + kb * 16)));
                    hacc[0][j] = hfma2u(a0.x, bb.x, hacc[0][j]);
                    hacc[0][j] = hfma2u(a0.y, bb.y, hacc[0][j]);
                    hacc[0][j] = hfma2u(a0.z, bb.z, hacc[0][j]);
                    hacc[0][j] = hfma2u(a0.w, bb.w, hacc[0][j]);
                    hacc[1][j] = hfma2u(a1.x, bb.x, hacc[1][j]);
                    hacc[1][j] = hfma2u(a1.y, bb.y, hacc[1][j]);
                    hacc[1][j] = hfma2u(a1.z, bb.z, hacc[1][j]);
                    hacc[1][j] = hfma2u(a1.w, bb.w, hacc[1][j]);
                }
            }
            #pragma unroll
            for (int j = 0; j < 8; j++) {
                float2 f0 = __half22float2(*(__half2*)&hacc[0][j]);
                float2 f1 = __half22float2(*(__half2*)&hacc[1][j]);
                facc[0][jh * 8 + j] += f0.x + f0.y;
                facc[1][jh * 8 + j] += f1.x + f1.y;
            }
        }
    };

    // ---- pipeline ----
    if (tid < 256) { loadG(0); storeS(0); loadG(1); }
    else if (valid) { loadGf(0); storeSf(0); loadGf(1); }

    for (int i = 0; i < NCHUNK; i++) {
        __syncthreads();
        if (i + 1 < NCHUNK) {
            const int s = (i + 1) % 3;
            if (tid < 256) storeS(s);
            else if (valid) storeSf(s);
        }
        if (i + 2 < NCHUNK) {
            if (tid < 256) loadG(i + 2);
            else if (valid) loadGf(i + 2);
        }
        if (wid < 8) compute(i % 3);
        else if (valid) fcompute(i % 3);
    }

    __syncthreads();   // all compute done; smem free for reduction overlay
    float* red = (float*)smem;    // [128][4]

    if (wid < 8) {
        // ---- HMMA epilogue: tanh + Va over 128 h, cross-warp reduce ----
        const int b = row0 >> 9;
        float va_r[8], uh_r[8];
        #pragma unroll
        for (int j = 0; j < 4; j++) {
            int col = h0 + wn + j * 8 + (lane & 3) * 2;
            va_r[j * 2 + 0] = __ldg(Va + col);
            va_r[j * 2 + 1] = __ldg(Va + col + 1);
            uh_r[j * 2 + 0] = __ldg(uh + b * Hz + col);
            uh_r[j * 2 + 1] = __ldg(uh + b * Hz + col + 1);
        }
        #pragma unroll
        for (int i = 0; i < 4; i++) {
            float s0 = 0.f, s1 = 0.f;
            #pragma unroll
            for (int j = 0; j < 4; j++) {
                s0 = fmaf(va_r[j*2+0], tanh_fast(acc[i][j][0] + uh_r[j*2+0]), s0);
                s0 = fmaf(va_r[j*2+1], tanh_fast(acc[i][j][1] + uh_r[j*2+1]), s0);
                s1 = fmaf(va_r[j*2+0], tanh_fast(acc[i][j][2] + uh_r[j*2+0]), s1);
                s1 = fmaf(va_r[j*2+1], tanh_fast(acc[i][j][3] + uh_r[j*2+1]), s1);
            }
            s0 += __shfl_xor_sync(0xffffffffu, s0, 1);
            s0 += __shfl_xor_sync(0xffffffffu, s0, 2);
            s1 += __shfl_xor_sync(0xffffffffu, s1, 1);
            s1 += __shfl_xor_sync(0xffffffffu, s1, 2);
            if ((lane & 3) == 0) {
                int r = wm + i * 16 + (lane >> 2);
                red[r * 4 + warp_n] = s0;
                red[(r + 8) * 4 + warp_n] = s1;
            }
        }
    } else if (valid) {
        // ---- fma epilogue: rows pool0+rt0(+1); 16 h-cols/thread; shfl over tc ----
        const int bp = pool0 >> 9;    // pool block is 32-aligned, single b
        #pragma unroll
        for (int r = 0; r < 2; r++) {
            float s = 0.f;
            #pragma unroll
            for (int jj = 0; jj < 16; jj++) {
                int h = h0 + jj * 8 + tc;
                float x = facc[r][jj] + __ldg(uh + bp * Hz + h);
                s = fmaf(__ldg(Va + h), tanh_fast(x), s);
            }
            s += __shfl_down_sync(0xffffffffu, s, 4, 8);
            s += __shfl_down_sync(0xffffffffu, s, 2, 8);
            s += __shfl_down_sync(0xffffffffu, s, 1, 8);
            if (tc == 0)
                partial[(size_t)blockIdx.x * BT + pool0 + rt0 + r] = s;
        }
    }
    __syncthreads();
    if (tid < 128) {
        float s = red[tid * 4] + red[tid * 4 + 1] +
                  red[tid * 4 + 2] + red[tid * 4 + 3];
        partial[(size_t)blockIdx.x * BT + row0 + tid] = s;
    }
}

// ---------------------------------------------------------------------------
// Kernel 3: sum partials + softmax over T. One block per b, 512 threads.
// ---------------------------------------------------------------------------
__global__ __launch_bounds__(512)
void softmax_kernel(const float* __restrict__ partial,
                    float* __restrict__ att) {
    const int b = blockIdx.x;
    const int t = threadIdx.x;
    float s = 0.f;
    #pragma unroll
    for (int p = 0; p < NBLK; p++)
        s += partial[(size_t)p * BT + b * Tz + t];

    __shared__ float red[Tz];
    red[t] = s;
    __syncthreads();
    for (int off = 256; off; off >>= 1) {
        if (t < off) red[t] = fmaxf(red[t], red[t + off]);
        __syncthreads();
    }
    float m = red[0];
    __syncthreads();
    float e = expf(s - m);
    red[t] = e;
    __syncthreads();
    for (int off = 256; off; off >>= 1) {
        if (t < off) red[t] += red[t + off];
        __syncthreads();
    }
    att[b * Tz + t] = e * (1.0f / red[0]);
}

// ---------------------------------------------------------------------------
// Kernel 4: wsum (4-way T split) + combine
// ---------------------------------------------------------------------------
__global__ __launch_bounds__(256)
void wsum_kernel(const float* __restrict__ frames,
                 const float* __restrict__ att,
                 float* __restrict__ wpart) {
    const int b = blockIdx.y, sp = blockIdx.z;
    const int d = (blockIdx.x * 256 + threadIdx.x) * 4;
    const int t0 = sp * 128;

    __shared__ float as[128];
    if (threadIdx.x < 128) as[threadIdx.x] = att[b * Tz + t0 + threadIdx.x];
    __syncthreads();

    const float* fb = frames + ((size_t)b * Tz + t0) * Dz + d;
    float4 a0 = {0,0,0,0}, a1 = {0,0,0,0}, a2 = {0,0,0,0}, a3 = {0,0,0,0};
    #pragma unroll 2
    for (int t = 0; t < 128; t += 4) {
        float4 f0 = *(const float4*)(fb + (size_t)(t + 0) * Dz);
        float4 f1 = *(const float4*)(fb + (size_t)(t + 1) * Dz);
        float4 f2 = *(const float4*)(fb + (size_t)(t + 2) * Dz);
        float4 f3 = *(const float4*)(fb + (size_t)(t + 3) * Dz);
        float w0 = as[t], w1 = as[t + 1], w2 = as[t + 2], w3 = as[t + 3];
        a0.x = fmaf(w0, f0.x, a0.x); a0.y = fmaf(w0, f0.y, a0.y);
        a0.z = fmaf(w0, f0.z, a0.z); a0.w = fmaf(w0, f0.w, a0.w);
        a1.x = fmaf(w1, f1.x, a1.x); a1.y = fmaf(w1, f1.y, a1.y);
        a1.z = fmaf(w1, f1.z, a1.z); a1.w = fmaf(w1, f1.w, a1.w);
        a2.x = fmaf(w2, f2.x, a2.x); a2.y = fmaf(w2, f2.y, a2.y);
        a2.z = fmaf(w2, f2.z, a2.z); a2.w = fmaf(w2, f2.w, a2.w);
        a3.x = fmaf(w3, f3.x, a3.x); a3.y = fmaf(w3, f3.y, a3.y);
        a3.z = fmaf(w3, f3.z, a3.z); a3.w = fmaf(w3, f3.w, a3.w);
    }
    float4 r;
    r.x = (a0.x + a1.x) + (a2.x + a3.x);
    r.y = (a0.y + a1.y) + (a2.y + a3.y);
    r.z = (a0.z + a1.z) + (a2.z + a3.z);
    r.w = (a0.w + a1.w) + (a2.w + a3.w);
    *(float4*)(wpart + (size_t)sp * (Bz * Dz) + b * Dz + d) = r;
}

__global__ __launch_bounds__(256)
void wsum_combine(const float* __restrict__ wpart, float* __restrict__ out) {
    const int i = (blockIdx.x * 256 + threadIdx.x) * 4;
    float4 a = *(const float4*)(wpart + i);
    float4 b4 = *(const float4*)(wpart + 1 * (Bz * Dz) + i);
    float4 c = *(const float4*)(wpart + 2 * (Bz * Dz) + i);
    float4 d4 = *(const float4*)(wpart + 3 * (Bz * Dz) + i);
    float4 r;
    r.x = (a.x + b4.x) + (c.x + d4.x);
    r.y = (a.y + b4.y) + (c.y + d4.y);
    r.z = (a.z + b4.z) + (c.z + d4.z);
    r.w = (a.w + b4.w) + (c.w + d4.w);
    *(float4*)(out + i) = r;
}

// ---------------------------------------------------------------------------
extern "C" void kernel_launch(void* const* d_in, const int* in_sizes, int n_in,
                              void* d_out, int out_size) {
    const float* frames = (const float*)d_in[0];
    const float* text   = (const float*)d_in[1];
    const float* Wa     = (const float*)d_in[2];
    const float* Ua     = (const float*)d_in[3];
    const float* Va     = (const float*)d_in[4];
    const float* ba     = (const float*)d_in[5];
    float* out          = (float*)d_out;

    float *uh, *partial, *att, *wpart;
    __half* WaT;
    cudaGetSymbolAddress((void**)&uh, g_uh);
    cudaGetSymbolAddress((void**)&partial, g_partial);
    cudaGetSymbolAddress((void**)&att, g_att);
    cudaGetSymbolAddress((void**)&WaT, g_WaT);
    cudaGetSymbolAddress((void**)&wpart, g_wpart);

    cudaFuncSetAttribute(score_hmma_kernel,
                         cudaFuncAttributeMaxDynamicSharedMemorySize, SM_TOTAL);

    transpose_kernel<<<dim3(Dz / 32, Hz / 32), dim3(32, 8)>>>(Wa, WaT);
    uh_kernel<<<dim3(Hz / 128, Bz / 8), 128>>>(text, Ua, ba, uh);
    // grid: x = h-block (4), y = row-block (205: 128 HMMA + 32 fma rows each)
    score_hmma_kernel<<<dim3(NBLK, RH), 384, SM_TOTAL>>>(
        frames, WaT, uh, Va, partial);
    softmax_kernel<<<Bz, Tz>>>(partial, att);
    wsum_kernel<<<dim3(2, Bz, 4), 256>>>(frames, att, wpart);
    wsum_combine<<<(Bz * Dz) / 1024, 256>>>(wpart, out);
}

// round 10
// speedup vs baseline: 2.4471x; 2.4471x over previous
#include <cuda_runtime.h>
#include <cuda_fp16.h>
#include <math.h>
#include <cstdint>

// Problem dims (fixed per reference)
#define Bz 64
#define Tz 512
#define Dz 2048
#define Hz 512
#define BT (Bz * Tz)          // 32768
#define NBLK 4                // H/128 h-blocks for partial scores

// Scratch (__device__ globals; allocation-free rule)
__device__ float g_uh[Bz * Hz];
__device__ float g_partial[NBLK * BT];
__device__ __half g_WaT[Hz * Dz];   // Wa transposed -> [H, D] fp16

// ---------------------------------------------------------------------------
// helpers
// ---------------------------------------------------------------------------
__device__ __forceinline__ uint32_t smem_u32(const void* p) {
    uint32_t a;
    asm("{ .reg .u64 t; cvta.to.shared.u64 t, %1; cvt.u32.u64 %0, t; }"
        : "=r"(a) : "l"(p));
    return a;
}

#define SWZ(o) ((o) ^ (((o) >> 3) & 0x70))

__device__ __forceinline__ void ldsm4(uint32_t* a, uint32_t addr) {
    asm volatile("ldmatrix.sync.aligned.m8n8.x4.shared.b16 {%0,%1,%2,%3}, [%4];"
                 : "=r"(a[0]), "=r"(a[1]), "=r"(a[2]), "=r"(a[3]) : "r"(addr));
}
// fp16 inputs, fp32 accumulate
__device__ __forceinline__ void mma16816(float* c, const uint32_t* a,
                                         const uint32_t* b) {
    asm volatile(
        "mma.sync.aligned.m16n8k16.row.col.f32.f16.f16.f32 "
        "{%0,%1,%2,%3}, {%4,%5,%6,%7}, {%8,%9}, {%0,%1,%2,%3};"
        : "+f"(c[0]), "+f"(c[1]), "+f"(c[2]), "+f"(c[3])
        : "r"(a[0]), "r"(a[1]), "r"(a[2]), "r"(a[3]), "r"(b[0]), "r"(b[1]));
}
__device__ __forceinline__ float tanh_fast(float x) {
    float y;
    asm("tanh.approx.f32 %0, %1;" : "=f"(y) : "f"(x));
    return y;
}

// ---------------------------------------------------------------------------
// Kernel 1 (fused prep): blocks [0,1024): WaT = fp16(Wa^T);
//                        blocks [1024,1040): Uh = text @ Ua + ba (fp32)
// 256 threads per block; the two jobs run concurrently in one launch.
// ---------------------------------------------------------------------------
__global__ __launch_bounds__(256)
void prep_kernel(const float* __restrict__ Wa,
                 const float* __restrict__ text,
                 const float* __restrict__ Ua,
                 const float* __restrict__ ba,
                 __half* __restrict__ WaT,
                 float* __restrict__ uh) {
    __shared__ float tile[32][33];      // transpose buffer
    __shared__ float ts[8][32];         // uh text tile
    const int tid = threadIdx.x;

    if (blockIdx.x < 1024) {
        // ---- transpose: 64 k-blocks x 16 n-blocks of 32x32 ----
        const int k0 = (blockIdx.x & 63) * 32;
        const int n0 = (blockIdx.x >> 6) * 32;
        const int tx = tid & 31, ty = tid >> 5;
        for (int i = ty; i < 32; i += 8)
            tile[i][tx] = Wa[(size_t)(k0 + i) * Hz + n0 + tx];
        __syncthreads();
        for (int i = ty; i < 32; i += 8)
            WaT[(size_t)(n0 + i) * Dz + k0 + tx] =
                __float2half_rn(tile[tx][i]);
    } else {
        // ---- uh: 2 h-blocks (256 wide) x 8 b-blocks (8 rows) ----
        const int blk = blockIdx.x - 1024;
        const int h  = (blk & 1) * 256 + tid;
        const int b0 = (blk >> 1) * 8;
        float acc[8] = {0.f, 0.f, 0.f, 0.f, 0.f, 0.f, 0.f, 0.f};

        for (int d0 = 0; d0 < Dz; d0 += 32) {
            {   // 8*32 = 256 values, one per thread
                int i = tid >> 5, k = tid & 31;
                ts[i][k] = text[(b0 + i) * Dz + d0 + k];
            }
            __syncthreads();
            #pragma unroll
            for (int k = 0; k < 32; k++) {
                float u = Ua[(size_t)(d0 + k) * Hz + h];
                #pragma unroll
                for (int i = 0; i < 8; i++) acc[i] = fmaf(ts[i][k], u, acc[i]);
            }
            __syncthreads();
        }
        float bav = ba[h];
        #pragma unroll
        for (int i = 0; i < 8; i++) uh[(b0 + i) * Hz + h] = acc[i] + bav;
    }
}

// ---------------------------------------------------------------------------
// Kernel 2: fp16 HMMA score GEMM (fp32 acc) + fused tanh·Va epilogue.
// CTA: M=128 rows (one b), N=128 h, 8 warps as 2(M) x 4(N), warp tile 64x32.
// K=2048 in 32 chunks of 64; triple-buffered smem, one sync per chunk.
// (R4 pipeline, verified at ~0.2% of the SIMT-mma pipe floor.)
// ---------------------------------------------------------------------------
#define ABUF(s) ((uint32_t)(s) * 16384u)            // 3 x 16KB
#define BBUF(s) (49152u + (uint32_t)(s) * 16384u)   // 3 x 16KB
#define SM_TOTAL 98304
#define NCHUNK 32

__global__ __launch_bounds__(256, 1)
void score_hmma_kernel(const float* __restrict__ frames,
                       const __half* __restrict__ WaT,
                       const float* __restrict__ uh,
                       const float* __restrict__ Va,
                       float* __restrict__ partial) {
    extern __shared__ char smem[];
    const uint32_t sbase = smem_u32(smem);
    const int tid = threadIdx.x;
    const int wid = tid >> 5, lane = tid & 31;
    const int warp_m = wid & 1, warp_n = wid >> 1;    // 2 x 4
    const int wm = warp_m * 64, wn = warp_n * 32;
    const int h0   = blockIdx.x * 128;
    const int row0 = blockIdx.y * 128;

    float acc[4][4][4];
    #pragma unroll
    for (int i = 0; i < 4; i++)
        #pragma unroll
        for (int j = 0; j < 4; j++)
            #pragma unroll
            for (int e = 0; e < 4; e++) acc[i][j][e] = 0.f;

    float4 pa[8], pb[4];

    // global -> regs for chunk c
    auto loadG = [&](int c) {
        const float* fA = frames + (size_t)row0 * Dz + c * 64;
        #pragma unroll
        for (int v = 0; v < 8; v++) {
            int idx = tid + v * 256;          // 128 rows x 16 float4
            int r = idx >> 4, c4 = (idx & 15) << 2;
            pa[v] = *(const float4*)(fA + (size_t)r * Dz + c4);
        }
        const __half* fB = WaT + (size_t)h0 * Dz + c * 64;
        #pragma unroll
        for (int v = 0; v < 4; v++) {
            int idx = tid + v * 256;          // 128 rows x 8 x16B
            int n = idx >> 3, k8 = (idx & 7) << 3;
            pb[v] = *(const float4*)(fB + (size_t)n * Dz + k8);
        }
    };
    // regs -> smem buffer (A converted fp32 -> fp16)
    auto storeS = [&](uint32_t aoff, uint32_t boff) {
        #pragma unroll
        for (int v = 0; v < 8; v++) {
            int idx = tid + v * 256;
            int r = idx >> 4, c4 = (idx & 15) << 2;
            __half2 p0 = __float22half2_rn(make_float2(pa[v].x, pa[v].y));
            __half2 p1 = __float22half2_rn(make_float2(pa[v].z, pa[v].w));
            uint2 pk;
            pk.x = *(uint32_t*)&p0;
            pk.y = *(uint32_t*)&p1;
            *(uint2*)(smem + aoff + SWZ((uint32_t)(r * 128 + c4 * 2))) = pk;
        }
        #pragma unroll
        for (int v = 0; v < 4; v++) {
            int idx = tid + v * 256;
            int n = idx >> 3, k8 = (idx & 7) << 3;
            *(float4*)(smem + boff + SWZ((uint32_t)(n * 128 + k8 * 2))) = pb[v];
        }
    };
    // compute on buffer (aoff, boff): 4 k16-steps
    auto compute = [&](uint32_t aoff, uint32_t boff) {
        #pragma unroll
        for (int ks = 0; ks < 4; ks++) {
            const int k16 = ks * 16;
            uint32_t bfr[4][2];
            #pragma unroll
            for (int jj = 0; jj < 2; jj++) {
                uint32_t r4[4];
                int g = lane >> 3;
                uint32_t off = (uint32_t)((wn + jj * 16 + (g >> 1) * 8 + (lane & 7)) * 128 +
                                          (k16 + (g & 1) * 8) * 2);
                ldsm4(r4, sbase + boff + SWZ(off));
                bfr[jj * 2 + 0][0] = r4[0]; bfr[jj * 2 + 0][1] = r4[1];
                bfr[jj * 2 + 1][0] = r4[2]; bfr[jj * 2 + 1][1] = r4[3];
            }
            #pragma unroll
            for (int i = 0; i < 4; i++) {
                uint32_t afr[4];
                uint32_t off = (uint32_t)((wm + i * 16 + (lane & 15)) * 128 +
                                          (k16 + (lane >> 4) * 8) * 2);
                ldsm4(afr, sbase + aoff + SWZ(off));
                #pragma unroll
                for (int j = 0; j < 4; j++)
                    mma16816(acc[i][j], afr, bfr[j]);
            }
        }
    };

    // Prologue: chunk0 -> buf0; chunk1 staged in regs
    loadG(0);
    storeS(ABUF(0), BBUF(0));
    loadG(1);

    for (int i = 0; i < NCHUNK; i++) {
        __syncthreads();   // all warps done computing chunk i-1; STS of chunk i visible
        if (i + 1 < NCHUNK) {
            const int s = (i + 1) % 3;
            storeS(ABUF(s), BBUF(s));          // regs hold chunk i+1
        }
        if (i + 2 < NCHUNK) loadG(i + 2);       // issue LDGs; land during compute
        const int s = i % 3;
        compute(ABUF(s), BBUF(s));
    }

    // ---- epilogue: tanh + Va-weighted sum over this CTA's 128 h-cols ----
    const int b = row0 >> 9;
    float va_r[8], uh_r[8];
    #pragma unroll
    for (int j = 0; j < 4; j++) {
        int col = h0 + wn + j * 8 + (lane & 3) * 2;
        va_r[j * 2 + 0] = __ldg(Va + col);
        va_r[j * 2 + 1] = __ldg(Va + col + 1);
        uh_r[j * 2 + 0] = __ldg(uh + b * Hz + col);
        uh_r[j * 2 + 1] = __ldg(uh + b * Hz + col + 1);
    }
    __syncthreads();
    float* red = (float*)smem;    // [128][4] overlay

    #pragma unroll
    for (int i = 0; i < 4; i++) {
        float s0 = 0.f, s1 = 0.f;
        #pragma unroll
        for (int j = 0; j < 4; j++) {
            s0 = fmaf(va_r[j*2+0], tanh_fast(acc[i][j][0] + uh_r[j*2+0]), s0);
            s0 = fmaf(va_r[j*2+1], tanh_fast(acc[i][j][1] + uh_r[j*2+1]), s0);
            s1 = fmaf(va_r[j*2+0], tanh_fast(acc[i][j][2] + uh_r[j*2+0]), s1);
            s1 = fmaf(va_r[j*2+1], tanh_fast(acc[i][j][3] + uh_r[j*2+1]), s1);
        }
        s0 += __shfl_xor_sync(0xffffffffu, s0, 1);
        s0 += __shfl_xor_sync(0xffffffffu, s0, 2);
        s1 += __shfl_xor_sync(0xffffffffu, s1, 1);
        s1 += __shfl_xor_sync(0xffffffffu, s1, 2);
        if ((lane & 3) == 0) {
            int r = wm + i * 16 + (lane >> 2);
            red[r * 4 + warp_n] = s0;
            red[(r + 8) * 4 + warp_n] = s1;
        }
    }
    __syncthreads();
    if (tid < 128) {
        float s = red[tid * 4] + red[tid * 4 + 1] +
                  red[tid * 4 + 2] + red[tid * 4 + 3];
        partial[(size_t)blockIdx.x * BT + row0 + tid] = s;
    }
}

// ---------------------------------------------------------------------------
// Kernel 3 (fused): per-CTA softmax recompute (from score partials, cheap)
// + weighted sum over frames. grid (8, B): CTA = (d-block of 256, batch b).
// No att/wpart round-trips, no separate softmax/combine launches.
// ---------------------------------------------------------------------------
__global__ __launch_bounds__(256)
void out_kernel(const float* __restrict__ partial,
                const float* __restrict__ frames,
                float* __restrict__ out) {
    const int b = blockIdx.y;
    const int tid = threadIdx.x;

    __shared__ float sc[Tz];
    __shared__ float red[256];

    // scores for this b (sum of NBLK h-block partials)
    #pragma unroll
    for (int t = tid; t < Tz; t += 256) {
        float s = 0.f;
        #pragma unroll
        for (int p = 0; p < NBLK; p++)
            s += partial[(size_t)p * BT + b * Tz + t];
        sc[t] = s;
    }
    __syncthreads();

    // max reduce
    red[tid] = fmaxf(sc[tid], sc[tid + 256]);
    __syncthreads();
    for (int off = 128; off; off >>= 1) {
        if (tid < off) red[tid] = fmaxf(red[tid], red[tid + off]);
        __syncthreads();
    }
    const float m = red[0];
    __syncthreads();

    // exp + sum reduce
    float e0 = expf(sc[tid] - m);
    float e1 = expf(sc[tid + 256] - m);
    red[tid] = e0 + e1;
    __syncthreads();
    for (int off = 128; off; off >>= 1) {
        if (tid < off) red[tid] += red[tid + off];
        __syncthreads();
    }
    const float inv = 1.0f / red[0];
    sc[tid]       = e0 * inv;
    sc[tid + 256] = e1 * inv;
    __syncthreads();

    // weighted sum: out[b, d] = sum_t sc[t] * frames[b,t,d]
    const int d = blockIdx.x * 256 + tid;
    const float* fb = frames + (size_t)b * Tz * Dz + d;
    float a0 = 0.f, a1 = 0.f, a2 = 0.f, a3 = 0.f;
    float a4 = 0.f, a5 = 0.f, a6 = 0.f, a7 = 0.f;
    #pragma unroll 2
    for (int t = 0; t < Tz; t += 8) {
        a0 = fmaf(sc[t + 0], fb[(size_t)(t + 0) * Dz], a0);
        a1 = fmaf(sc[t + 1], fb[(size_t)(t + 1) * Dz], a1);
        a2 = fmaf(sc[t + 2], fb[(size_t)(t + 2) * Dz], a2);
        a3 = fmaf(sc[t + 3], fb[(size_t)(t + 3) * Dz], a3);
        a4 = fmaf(sc[t + 4], fb[(size_t)(t + 4) * Dz], a4);
        a5 = fmaf(sc[t + 5], fb[(size_t)(t + 5) * Dz], a5);
        a6 = fmaf(sc[t + 6], fb[(size_t)(t + 6) * Dz], a6);
        a7 = fmaf(sc[t + 7], fb[(size_t)(t + 7) * Dz], a7);
    }
    out[b * Dz + d] = ((a0 + a1) + (a2 + a3)) + ((a4 + a5) + (a6 + a7));
}

// ---------------------------------------------------------------------------
extern "C" void kernel_launch(void* const* d_in, const int* in_sizes, int n_in,
                              void* d_out, int out_size) {
    const float* frames = (const float*)d_in[0];
    const float* text   = (const float*)d_in[1];
    const float* Wa     = (const float*)d_in[2];
    const float* Ua     = (const float*)d_in[3];
    const float* Va     = (const float*)d_in[4];
    const float* ba     = (const float*)d_in[5];
    float* out          = (float*)d_out;

    float *uh, *partial;
    __half* WaT;
    cudaGetSymbolAddress((void**)&uh, g_uh);
    cudaGetSymbolAddress((void**)&partial, g_partial);
    cudaGetSymbolAddress((void**)&WaT, g_WaT);

    cudaFuncSetAttribute(score_hmma_kernel,
                         cudaFuncAttributeMaxDynamicSharedMemorySize, SM_TOTAL);

    // 1) fused: Wa -> WaT (fp16 transpose)  ||  Uh = text @ Ua + ba
    prep_kernel<<<1040, 256>>>(Wa, text, Ua, ba, WaT, uh);

    // 2) HMMA score GEMM + tanh·Va epilogue (partials per h-block)
    score_hmma_kernel<<<dim3(NBLK, BT / 128), 256, SM_TOTAL>>>(
        frames, WaT, uh, Va, partial);

    // 3) fused softmax + weighted sum
    out_kernel<<<dim3(Dz / 256, Bz), 256>>>(partial, frames, out);
}

// round 11
// speedup vs baseline: 2.4605x; 1.0055x over previous
#include <cuda_runtime.h>
#include <cuda_fp16.h>
#include <math.h>
#include <cstdint>

// Problem dims (fixed per reference)
#define Bz 64
#define Tz 512
#define Dz 2048
#define Hz 512
#define BT (Bz * Tz)          // 32768
#define NBLK 4                // H/128 h-blocks for partial scores

// Scratch (__device__ globals; allocation-free rule)
__device__ float g_uh[Bz * Hz];
__device__ float g_partial[NBLK * BT];
__device__ __half g_WaT[Hz * Dz];   // Wa transposed -> [H, D] fp16

// ---------------------------------------------------------------------------
// helpers
// ---------------------------------------------------------------------------
__device__ __forceinline__ uint32_t smem_u32(const void* p) {
    uint32_t a;
    asm("{ .reg .u64 t; cvta.to.shared.u64 t, %1; cvt.u32.u64 %0, t; }"
        : "=r"(a) : "l"(p));
    return a;
}

#define SWZ(o) ((o) ^ (((o) >> 3) & 0x70))

__device__ __forceinline__ void ldsm4(uint32_t* a, uint32_t addr) {
    asm volatile("ldmatrix.sync.aligned.m8n8.x4.shared.b16 {%0,%1,%2,%3}, [%4];"
                 : "=r"(a[0]), "=r"(a[1]), "=r"(a[2]), "=r"(a[3]) : "r"(addr));
}
// fp16 inputs, fp32 accumulate
__device__ __forceinline__ void mma16816(float* c, const uint32_t* a,
                                         const uint32_t* b) {
    asm volatile(
        "mma.sync.aligned.m16n8k16.row.col.f32.f16.f16.f32 "
        "{%0,%1,%2,%3}, {%4,%5,%6,%7}, {%8,%9}, {%0,%1,%2,%3};"
        : "+f"(c[0]), "+f"(c[1]), "+f"(c[2]), "+f"(c[3])
        : "r"(a[0]), "r"(a[1]), "r"(a[2]), "r"(a[3]), "r"(b[0]), "r"(b[1]));
}
__device__ __forceinline__ float tanh_fast(float x) {
    float y;
    asm("tanh.approx.f32 %0, %1;" : "=f"(y) : "f"(x));
    return y;
}

// ---------------------------------------------------------------------------
// Kernel 1 (fused prep): blocks [0,1024): WaT = fp16(Wa^T);
//                        blocks [1024,1040): Uh = text @ Ua + ba (fp32)
// 256 threads per block; the two jobs run concurrently in one launch.
// ---------------------------------------------------------------------------
__global__ __launch_bounds__(256)
void prep_kernel(const float* __restrict__ Wa,
                 const float* __restrict__ text,
                 const float* __restrict__ Ua,
                 const float* __restrict__ ba,
                 __half* __restrict__ WaT,
                 float* __restrict__ uh) {
    __shared__ float tile[32][33];      // transpose buffer
    __shared__ float ts[8][32];         // uh text tile
    const int tid = threadIdx.x;

    if (blockIdx.x < 1024) {
        // ---- transpose: 64 k-blocks x 16 n-blocks of 32x32 ----
        const int k0 = (blockIdx.x & 63) * 32;
        const int n0 = (blockIdx.x >> 6) * 32;
        const int tx = tid & 31, ty = tid >> 5;
        for (int i = ty; i < 32; i += 8)
            tile[i][tx] = Wa[(size_t)(k0 + i) * Hz + n0 + tx];
        __syncthreads();
        for (int i = ty; i < 32; i += 8)
            WaT[(size_t)(n0 + i) * Dz + k0 + tx] =
                __float2half_rn(tile[tx][i]);
    } else {
        // ---- uh: 2 h-blocks (256 wide) x 8 b-blocks (8 rows) ----
        const int blk = blockIdx.x - 1024;
        const int h  = (blk & 1) * 256 + tid;
        const int b0 = (blk >> 1) * 8;
        float acc[8] = {0.f, 0.f, 0.f, 0.f, 0.f, 0.f, 0.f, 0.f};

        for (int d0 = 0; d0 < Dz; d0 += 32) {
            {   // 8*32 = 256 values, one per thread
                int i = tid >> 5, k = tid & 31;
                ts[i][k] = text[(b0 + i) * Dz + d0 + k];
            }
            __syncthreads();
            #pragma unroll
            for (int k = 0; k < 32; k++) {
                float u = Ua[(size_t)(d0 + k) * Hz + h];
                #pragma unroll
                for (int i = 0; i < 8; i++) acc[i] = fmaf(ts[i][k], u, acc[i]);
            }
            __syncthreads();
        }
        float bav = ba[h];
        #pragma unroll
        for (int i = 0; i < 8; i++) uh[(b0 + i) * Hz + h] = acc[i] + bav;
    }
}

// ---------------------------------------------------------------------------
// Kernel 2: fp16 HMMA score GEMM (fp32 acc) + fused tanh·Va epilogue.
// CTA: M=128 rows (one b), N=128 h, 8 warps as 2(M) x 4(N), warp tile 64x32.
// K=2048 in 32 chunks of 64; triple-buffered smem, one sync per chunk.
// (R4 pipeline, verified at ~0.2% of the SIMT-mma pipe floor.)
// ---------------------------------------------------------------------------
#define ABUF(s) ((uint32_t)(s) * 16384u)            // 3 x 16KB
#define BBUF(s) (49152u + (uint32_t)(s) * 16384u)   // 3 x 16KB
#define SM_TOTAL 98304
#define NCHUNK 32

__global__ __launch_bounds__(256, 1)
void score_hmma_kernel(const float* __restrict__ frames,
                       const __half* __restrict__ WaT,
                       const float* __restrict__ uh,
                       const float* __restrict__ Va,
                       float* __restrict__ partial) {
    extern __shared__ char smem[];
    const uint32_t sbase = smem_u32(smem);
    const int tid = threadIdx.x;
    const int wid = tid >> 5, lane = tid & 31;
    const int warp_m = wid & 1, warp_n = wid >> 1;    // 2 x 4
    const int wm = warp_m * 64, wn = warp_n * 32;
    const int h0   = blockIdx.x * 128;
    const int row0 = blockIdx.y * 128;

    float acc[4][4][4];
    #pragma unroll
    for (int i = 0; i < 4; i++)
        #pragma unroll
        for (int j = 0; j < 4; j++)
            #pragma unroll
            for (int e = 0; e < 4; e++) acc[i][j][e] = 0.f;

    float4 pa[8], pb[4];

    // global -> regs for chunk c
    auto loadG = [&](int c) {
        const float* fA = frames + (size_t)row0 * Dz + c * 64;
        #pragma unroll
        for (int v = 0; v < 8; v++) {
            int idx = tid + v * 256;          // 128 rows x 16 float4
            int r = idx >> 4, c4 = (idx & 15) << 2;
            pa[v] = *(const float4*)(fA + (size_t)r * Dz + c4);
        }
        const __half* fB = WaT + (size_t)h0 * Dz + c * 64;
        #pragma unroll
        for (int v = 0; v < 4; v++) {
            int idx = tid + v * 256;          // 128 rows x 8 x16B
            int n = idx >> 3, k8 = (idx & 7) << 3;
            pb[v] = *(const float4*)(fB + (size_t)n * Dz + k8);
        }
    };
    // regs -> smem buffer (A converted fp32 -> fp16)
    auto storeS = [&](uint32_t aoff, uint32_t boff) {
        #pragma unroll
        for (int v = 0; v < 8; v++) {
            int idx = tid + v * 256;
            int r = idx >> 4, c4 = (idx & 15) << 2;
            __half2 p0 = __float22half2_rn(make_float2(pa[v].x, pa[v].y));
            __half2 p1 = __float22half2_rn(make_float2(pa[v].z, pa[v].w));
            uint2 pk;
            pk.x = *(uint32_t*)&p0;
            pk.y = *(uint32_t*)&p1;
            *(uint2*)(smem + aoff + SWZ((uint32_t)(r * 128 + c4 * 2))) = pk;
        }
        #pragma unroll
        for (int v = 0; v < 4; v++) {
            int idx = tid + v * 256;
            int n = idx >> 3, k8 = (idx & 7) << 3;
            *(float4*)(smem + boff + SWZ((uint32_t)(n * 128 + k8 * 2))) = pb[v];
        }
    };
    // compute on buffer (aoff, boff): 4 k16-steps
    auto compute = [&](uint32_t aoff, uint32_t boff) {
        #pragma unroll
        for (int ks = 0; ks < 4; ks++) {
            const int k16 = ks * 16;
            uint32_t bfr[4][2];
            #pragma unroll
            for (int jj = 0; jj < 2; jj++) {
                uint32_t r4[4];
                int g = lane >> 3;
                uint32_t off = (uint32_t)((wn + jj * 16 + (g >> 1) * 8 + (lane & 7)) * 128 +
                                          (k16 + (g & 1) * 8) * 2);
                ldsm4(r4, sbase + boff + SWZ(off));
                bfr[jj * 2 + 0][0] = r4[0]; bfr[jj * 2 + 0][1] = r4[1];
                bfr[jj * 2 + 1][0] = r4[2]; bfr[jj * 2 + 1][1] = r4[3];
            }
            #pragma unroll
            for (int i = 0; i < 4; i++) {
                uint32_t afr[4];
                uint32_t off = (uint32_t)((wm + i * 16 + (lane & 15)) * 128 +
                                          (k16 + (lane >> 4) * 8) * 2);
                ldsm4(afr, sbase + aoff + SWZ(off));
                #pragma unroll
                for (int j = 0; j < 4; j++)
                    mma16816(acc[i][j], afr, bfr[j]);
            }
        }
    };

    // Prologue: chunk0 -> buf0; chunk1 staged in regs
    loadG(0);
    storeS(ABUF(0), BBUF(0));
    loadG(1);

    for (int i = 0; i < NCHUNK; i++) {
        __syncthreads();   // all warps done computing chunk i-1; STS of chunk i visible
        if (i + 1 < NCHUNK) {
            const int s = (i + 1) % 3;
            storeS(ABUF(s), BBUF(s));          // regs hold chunk i+1
        }
        if (i + 2 < NCHUNK) loadG(i + 2);       // issue LDGs; land during compute
        const int s = i % 3;
        compute(ABUF(s), BBUF(s));
    }

    // ---- epilogue: tanh + Va-weighted sum over this CTA's 128 h-cols ----
    const int b = row0 >> 9;
    float va_r[8], uh_r[8];
    #pragma unroll
    for (int j = 0; j < 4; j++) {
        int col = h0 + wn + j * 8 + (lane & 3) * 2;
        va_r[j * 2 + 0] = __ldg(Va + col);
        va_r[j * 2 + 1] = __ldg(Va + col + 1);
        uh_r[j * 2 + 0] = __ldg(uh + b * Hz + col);
        uh_r[j * 2 + 1] = __ldg(uh + b * Hz + col + 1);
    }
    __syncthreads();
    float* red = (float*)smem;    // [128][4] overlay

    #pragma unroll
    for (int i = 0; i < 4; i++) {
        float s0 = 0.f, s1 = 0.f;
        #pragma unroll
        for (int j = 0; j < 4; j++) {
            s0 = fmaf(va_r[j*2+0], tanh_fast(acc[i][j][0] + uh_r[j*2+0]), s0);
            s0 = fmaf(va_r[j*2+1], tanh_fast(acc[i][j][1] + uh_r[j*2+1]), s0);
            s1 = fmaf(va_r[j*2+0], tanh_fast(acc[i][j][2] + uh_r[j*2+0]), s1);
            s1 = fmaf(va_r[j*2+1], tanh_fast(acc[i][j][3] + uh_r[j*2+1]), s1);
        }
        s0 += __shfl_xor_sync(0xffffffffu, s0, 1);
        s0 += __shfl_xor_sync(0xffffffffu, s0, 2);
        s1 += __shfl_xor_sync(0xffffffffu, s1, 1);
        s1 += __shfl_xor_sync(0xffffffffu, s1, 2);
        if ((lane & 3) == 0) {
            int r = wm + i * 16 + (lane >> 2);
            red[r * 4 + warp_n] = s0;
            red[(r + 8) * 4 + warp_n] = s1;
        }
    }
    __syncthreads();
    if (tid < 128) {
        float s = red[tid * 4] + red[tid * 4 + 1] +
                  red[tid * 4 + 2] + red[tid * 4 + 3];
        partial[(size_t)blockIdx.x * BT + row0 + tid] = s;
    }
}

// ---------------------------------------------------------------------------
// Kernel 3 (fused): per-CTA softmax recompute (from score partials, cheap)
// + weighted sum over frames. grid (8, B): CTA = (d-block of 256, batch b).
// No att/wpart round-trips, no separate softmax/combine launches.
// ---------------------------------------------------------------------------
__global__ __launch_bounds__(256)
void out_kernel(const float* __restrict__ partial,
                const float* __restrict__ frames,
                float* __restrict__ out) {
    const int b = blockIdx.y;
    const int tid = threadIdx.x;

    __shared__ float sc[Tz];
    __shared__ float red[256];

    // scores for this b (sum of NBLK h-block partials)
    #pragma unroll
    for (int t = tid; t < Tz; t += 256) {
        float s = 0.f;
        #pragma unroll
        for (int p = 0; p < NBLK; p++)
            s += partial[(size_t)p * BT + b * Tz + t];
        sc[t] = s;
    }
    __syncthreads();

    // max reduce
    red[tid] = fmaxf(sc[tid], sc[tid + 256]);
    __syncthreads();
    for (int off = 128; off; off >>= 1) {
        if (tid < off) red[tid] = fmaxf(red[tid], red[tid + off]);
        __syncthreads();
    }
    const float m = red[0];
    __syncthreads();

    // exp + sum reduce
    float e0 = expf(sc[tid] - m);
    float e1 = expf(sc[tid + 256] - m);
    red[tid] = e0 + e1;
    __syncthreads();
    for (int off = 128; off; off >>= 1) {
        if (tid < off) red[tid] += red[tid + off];
        __syncthreads();
    }
    const float inv = 1.0f / red[0];
    sc[tid]       = e0 * inv;
    sc[tid + 256] = e1 * inv;
    __syncthreads();

    // weighted sum: out[b, d] = sum_t sc[t] * frames[b,t,d]
    const int d = blockIdx.x * 256 + tid;
    const float* fb = frames + (size_t)b * Tz * Dz + d;
    float a0 = 0.f, a1 = 0.f, a2 = 0.f, a3 = 0.f;
    float a4 = 0.f, a5 = 0.f, a6 = 0.f, a7 = 0.f;
    #pragma unroll 2
    for (int t = 0; t < Tz; t += 8) {
        a0 = fmaf(sc[t + 0], fb[(size_t)(t + 0) * Dz], a0);
        a1 = fmaf(sc[t + 1], fb[(size_t)(t + 1) * Dz], a1);
        a2 = fmaf(sc[t + 2], fb[(size_t)(t + 2) * Dz], a2);
        a3 = fmaf(sc[t + 3], fb[(size_t)(t + 3) * Dz], a3);
        a4 = fmaf(sc[t + 4], fb[(size_t)(t + 4) * Dz], a4);
        a5 = fmaf(sc[t + 5], fb[(size_t)(t + 5) * Dz], a5);
        a6 = fmaf(sc[t + 6], fb[(size_t)(t + 6) * Dz], a6);
        a7 = fmaf(sc[t + 7], fb[(size_t)(t + 7) * Dz], a7);
    }
    out[b * Dz + d] = ((a0 + a1) + (a2 + a3)) + ((a4 + a5) + (a6 + a7));
}

// ---------------------------------------------------------------------------
extern "C" void kernel_launch(void* const* d_in, const int* in_sizes, int n_in,
                              void* d_out, int out_size) {
    const float* frames = (const float*)d_in[0];
    const float* text   = (const float*)d_in[1];
    const float* Wa     = (const float*)d_in[2];
    const float* Ua     = (const float*)d_in[3];
    const float* Va     = (const float*)d_in[4];
    const float* ba     = (const float*)d_in[5];
    float* out          = (float*)d_out;

    float *uh, *partial;
    __half* WaT;
    cudaGetSymbolAddress((void**)&uh, g_uh);
    cudaGetSymbolAddress((void**)&partial, g_partial);
    cudaGetSymbolAddress((void**)&WaT, g_WaT);

    cudaFuncSetAttribute(score_hmma_kernel,
                         cudaFuncAttributeMaxDynamicSharedMemorySize, SM_TOTAL);

    // 1) fused: Wa -> WaT (fp16 transpose)  ||  Uh = text @ Ua + ba
    prep_kernel<<<1040, 256>>>(Wa, text, Ua, ba, WaT, uh);

    // 2) HMMA score GEMM + tanh·Va epilogue (partials per h-block)
    score_hmma_kernel<<<dim3(NBLK, BT / 128), 256, SM_TOTAL>>>(
        frames, WaT, uh, Va, partial);

    // 3) fused softmax + weighted sum
    out_kernel<<<dim3(Dz / 256, Bz), 256>>>(partial, frames, out);
}

// round 13
// speedup vs baseline: 3.9054x; 1.5872x over previous
#include <cuda_runtime.h>
#include <cuda_fp16.h>
#include <math.h>
#include <cstdint>

// Problem dims (fixed per reference)
#define Bz 64
#define Tz 512
#define Dz 2048
#define Hz 512
#define BT (Bz * Tz)          // 32768
#define NBLK 4                // H/128 h-blocks for partial scores
#define KSPL 8                // uh K-splits

// Scratch (__device__ globals; allocation-free rule)
__device__ float g_uhp[KSPL * Bz * Hz];   // uh K-split partials
__device__ float g_partial[NBLK * BT];
__device__ __half g_WaT[Hz * Dz];         // Wa transposed -> [H, D] fp16

// ---------------------------------------------------------------------------
// helpers
// ---------------------------------------------------------------------------
__device__ __forceinline__ uint32_t smem_u32(const void* p) {
    uint32_t a;
    asm("{ .reg .u64 t; cvta.to.shared.u64 t, %1; cvt.u32.u64 %0, t; }"
        : "=r"(a) : "l"(p));
    return a;
}

#define SWZ(o) ((o) ^ (((o) >> 3) & 0x70))

__device__ __forceinline__ void ldsm4(uint32_t* a, uint32_t addr) {
    asm volatile("ldmatrix.sync.aligned.m8n8.x4.shared.b16 {%0,%1,%2,%3}, [%4];"
                 : "=r"(a[0]), "=r"(a[1]), "=r"(a[2]), "=r"(a[3]) : "r"(addr));
}
// fp16 inputs, fp32 accumulate
__device__ __forceinline__ void mma16816(float* c, const uint32_t* a,
                                         const uint32_t* b) {
    asm volatile(
        "mma.sync.aligned.m16n8k16.row.col.f32.f16.f16.f32 "
        "{%0,%1,%2,%3}, {%4,%5,%6,%7}, {%8,%9}, {%0,%1,%2,%3};"
        : "+f"(c[0]), "+f"(c[1]), "+f"(c[2]), "+f"(c[3])
        : "r"(a[0]), "r"(a[1]), "r"(a[2]), "r"(a[3]), "r"(b[0]), "r"(b[1]));
}
__device__ __forceinline__ float tanh_fast(float x) {
    float y;
    asm("tanh.approx.f32 %0, %1;" : "=f"(y) : "f"(x));
    return y;
}

// ---------------------------------------------------------------------------
// Kernel 1 (fused prep):
//   blocks [0,1024)     : WaT = fp16(Wa^T)              (32x32 tiles)
//   blocks [1024,1152)  : uh partials, K-split 8:
//       uhp[ks][b][h] = sum_{d in slice ks} text[b,d]*Ua[d,h]  (+ba at ks=0)
// 256 threads per block; both jobs in one launch, fully parallel.
// ---------------------------------------------------------------------------
__global__ __launch_bounds__(256)
void prep_kernel(const float* __restrict__ Wa,
                 const float* __restrict__ text,
                 const float* __restrict__ Ua,
                 const float* __restrict__ ba,
                 __half* __restrict__ WaT,
                 float* __restrict__ uhp) {
    __shared__ float tile[32][33];      // transpose buffer
    __shared__ float ts[8][32];         // uh text tile
    const int tid = threadIdx.x;

    if (blockIdx.x < 1024) {
        // ---- transpose: 64 k-blocks x 16 n-blocks of 32x32 ----
        const int k0 = (blockIdx.x & 63) * 32;
        const int n0 = (blockIdx.x >> 6) * 32;
        const int tx = tid & 31, ty = tid >> 5;
        for (int i = ty; i < 32; i += 8)
            tile[i][tx] = Wa[(size_t)(k0 + i) * Hz + n0 + tx];
        __syncthreads();
        for (int i = ty; i < 32; i += 8)
            WaT[(size_t)(n0 + i) * Dz + k0 + tx] =
                __float2half_rn(tile[tx][i]);
    } else {
        // ---- uh partials: blk = hb(2) x bb(8) x ks(8) ----
        const int blk = blockIdx.x - 1024;       // 0..127
        const int hb = blk & 1;
        const int bb = (blk >> 1) & 7;
        const int ks = blk >> 4;
        const int h  = hb * 256 + tid;
        const int b0 = bb * 8;
        const int d_lo = ks * (Dz / KSPL);       // 256-wide K slice
        const int d_hi = d_lo + (Dz / KSPL);
        float acc[8] = {0.f, 0.f, 0.f, 0.f, 0.f, 0.f, 0.f, 0.f};

        for (int d0 = d_lo; d0 < d_hi; d0 += 32) {
            {   // 8*32 = 256 values, one per thread
                int i = tid >> 5, k = tid & 31;
                ts[i][k] = text[(b0 + i) * Dz + d0 + k];
            }
            __syncthreads();
            #pragma unroll
            for (int k = 0; k < 32; k++) {
                float u = Ua[(size_t)(d0 + k) * Hz + h];
                #pragma unroll
                for (int i = 0; i < 8; i++) acc[i] = fmaf(ts[i][k], u, acc[i]);
            }
            __syncthreads();
        }
        const float bav = (ks == 0) ? ba[h] : 0.f;
        float* dst = uhp + (size_t)ks * (Bz * Hz);
        #pragma unroll
        for (int i = 0; i < 8; i++) dst[(b0 + i) * Hz + h] = acc[i] + bav;
    }
}

// ---------------------------------------------------------------------------
// Kernel 2: fp16 HMMA score GEMM (fp32 acc) + fused tanh·Va epilogue.
// CTA: M=128 rows (one b), N=128 h, 8 warps as 2(M) x 4(N), warp tile 64x32.
// K=2048 in 32 chunks of 64; triple-buffered smem, one sync per chunk.
// Epilogue sums the 8 uh K-split partials when loading uh.
// ---------------------------------------------------------------------------
#define ABUF(s) ((uint32_t)(s) * 16384u)            // 3 x 16KB
#define BBUF(s) (49152u + (uint32_t)(s) * 16384u)   // 3 x 16KB
#define SM_TOTAL 98304
#define NCHUNK 32

__global__ __launch_bounds__(256, 1)
void score_hmma_kernel(const float* __restrict__ frames,
                       const __half* __restrict__ WaT,
                       const float* __restrict__ uhp,
                       const float* __restrict__ Va,
                       float* __restrict__ partial) {
    extern __shared__ char smem[];
    const uint32_t sbase = smem_u32(smem);
    const int tid = threadIdx.x;
    const int wid = tid >> 5, lane = tid & 31;
    const int warp_m = wid & 1, warp_n = wid >> 1;    // 2 x 4
    const int wm = warp_m * 64, wn = warp_n * 32;
    const int h0   = blockIdx.x * 128;
    const int row0 = blockIdx.y * 128;

    float acc[4][4][4];
    #pragma unroll
    for (int i = 0; i < 4; i++)
        #pragma unroll
        for (int j = 0; j < 4; j++)
            #pragma unroll
            for (int e = 0; e < 4; e++) acc[i][j][e] = 0.f;

    float4 pa[8], pb[4];

    // global -> regs for chunk c
    auto loadG = [&](int c) {
        const float* fA = frames + (size_t)row0 * Dz + c * 64;
        #pragma unroll
        for (int v = 0; v < 8; v++) {
            int idx = tid + v * 256;          // 128 rows x 16 float4
            int r = idx >> 4, c4 = (idx & 15) << 2;
            pa[v] = *(const float4*)(fA + (size_t)r * Dz + c4);
        }
        const __half* fB = WaT + (size_t)h0 * Dz + c * 64;
        #pragma unroll
        for (int v = 0; v < 4; v++) {
            int idx = tid + v * 256;          // 128 rows x 8 x16B
            int n = idx >> 3, k8 = (idx & 7) << 3;
            pb[v] = *(const float4*)(fB + (size_t)n * Dz + k8);
        }
    };
    // regs -> smem buffer (A converted fp32 -> fp16)
    auto storeS = [&](uint32_t aoff, uint32_t boff) {
        #pragma unroll
        for (int v = 0; v < 8; v++) {
            int idx = tid + v * 256;
            int r = idx >> 4, c4 = (idx & 15) << 2;
            __half2 p0 = __float22half2_rn(make_float2(pa[v].x, pa[v].y));
            __half2 p1 = __float22half2_rn(make_float2(pa[v].z, pa[v].w));
            uint2 pk;
            pk.x = *(uint32_t*)&p0;
            pk.y = *(uint32_t*)&p1;
            *(uint2*)(smem + aoff + SWZ((uint32_t)(r * 128 + c4 * 2))) = pk;
        }
        #pragma unroll
        for (int v = 0; v < 4; v++) {
            int idx = tid + v * 256;
            int n = idx >> 3, k8 = (idx & 7) << 3;
            *(float4*)(smem + boff + SWZ((uint32_t)(n * 128 + k8 * 2))) = pb[v];
        }
    };
    // compute on buffer (aoff, boff): 4 k16-steps
    auto compute = [&](uint32_t aoff, uint32_t boff) {
        #pragma unroll
        for (int ks = 0; ks < 4; ks++) {
            const int k16 = ks * 16;
            uint32_t bfr[4][2];
            #pragma unroll
            for (int jj = 0; jj < 2; jj++) {
                uint32_t r4[4];
                int g = lane >> 3;
                uint32_t off = (uint32_t)((wn + jj * 16 + (g >> 1) * 8 + (lane & 7)) * 128 +
                                          (k16 + (g & 1) * 8) * 2);
                ldsm4(r4, sbase + boff + SWZ(off));
                bfr[jj * 2 + 0][0] = r4[0]; bfr[jj * 2 + 0][1] = r4[1];
                bfr[jj * 2 + 1][0] = r4[2]; bfr[jj * 2 + 1][1] = r4[3];
            }
            #pragma unroll
            for (int i = 0; i < 4; i++) {
                uint32_t afr[4];
                uint32_t off = (uint32_t)((wm + i * 16 + (lane & 15)) * 128 +
                                          (k16 + (lane >> 4) * 8) * 2);
                ldsm4(afr, sbase + aoff + SWZ(off));
                #pragma unroll
                for (int j = 0; j < 4; j++)
                    mma16816(acc[i][j], afr, bfr[j]);
            }
        }
    };

    // Prologue: chunk0 -> buf0; chunk1 staged in regs
    loadG(0);
    storeS(ABUF(0), BBUF(0));
    loadG(1);

    for (int i = 0; i < NCHUNK; i++) {
        __syncthreads();   // all warps done computing chunk i-1; STS of chunk i visible
        if (i + 1 < NCHUNK) {
            const int s = (i + 1) % 3;
            storeS(ABUF(s), BBUF(s));          // regs hold chunk i+1
        }
        if (i + 2 < NCHUNK) loadG(i + 2);       // issue LDGs; land during compute
        const int s = i % 3;
        compute(ABUF(s), BBUF(s));
    }

    // ---- epilogue: tanh + Va-weighted sum over this CTA's 128 h-cols ----
    const int b = row0 >> 9;
    float va_r[8], uh_r[8];
    #pragma unroll
    for (int j = 0; j < 4; j++) {
        int col = h0 + wn + j * 8 + (lane & 3) * 2;
        va_r[j * 2 + 0] = __ldg(Va + col);
        va_r[j * 2 + 1] = __ldg(Va + col + 1);
        float u0 = 0.f, u1 = 0.f;
        #pragma unroll
        for (int p = 0; p < KSPL; p++) {
            const float* up = uhp + (size_t)p * (Bz * Hz) + b * Hz + col;
            u0 += __ldg(up);
            u1 += __ldg(up + 1);
        }
        uh_r[j * 2 + 0] = u0;
        uh_r[j * 2 + 1] = u1;
    }
    __syncthreads();
    float* red = (float*)smem;    // [128][4] overlay

    #pragma unroll
    for (int i = 0; i < 4; i++) {
        float s0 = 0.f, s1 = 0.f;
        #pragma unroll
        for (int j = 0; j < 4; j++) {
            s0 = fmaf(va_r[j*2+0], tanh_fast(acc[i][j][0] + uh_r[j*2+0]), s0);
            s0 = fmaf(va_r[j*2+1], tanh_fast(acc[i][j][1] + uh_r[j*2+1]), s0);
            s1 = fmaf(va_r[j*2+0], tanh_fast(acc[i][j][2] + uh_r[j*2+0]), s1);
            s1 = fmaf(va_r[j*2+1], tanh_fast(acc[i][j][3] + uh_r[j*2+1]), s1);
        }
        s0 += __shfl_xor_sync(0xffffffffu, s0, 1);
        s0 += __shfl_xor_sync(0xffffffffu, s0, 2);
        s1 += __shfl_xor_sync(0xffffffffu, s1, 1);
        s1 += __shfl_xor_sync(0xffffffffu, s1, 2);
        if ((lane & 3) == 0) {
            int r = wm + i * 16 + (lane >> 2);
            red[r * 4 + warp_n] = s0;
            red[(r + 8) * 4 + warp_n] = s1;
        }
    }
    __syncthreads();
    if (tid < 128) {
        float s = red[tid * 4] + red[tid * 4 + 1] +
                  red[tid * 4 + 2] + red[tid * 4 + 3];
        partial[(size_t)blockIdx.x * BT + row0 + tid] = s;
    }
}

// ---------------------------------------------------------------------------
// Kernel 3 (fused): per-CTA softmax recompute (from score partials, cheap)
// + weighted sum over frames. grid (8, B): CTA = (d-block of 256, batch b).
// ---------------------------------------------------------------------------
__global__ __launch_bounds__(256)
void out_kernel(const float* __restrict__ partial,
                const float* __restrict__ frames,
                float* __restrict__ out) {
    const int b = blockIdx.y;
    const int tid = threadIdx.x;

    __shared__ float sc[Tz];
    __shared__ float red[256];

    // scores for this b (sum of NBLK h-block partials)
    #pragma unroll
    for (int t = tid; t < Tz; t += 256) {
        float s = 0.f;
        #pragma unroll
        for (int p = 0; p < NBLK; p++)
            s += partial[(size_t)p * BT + b * Tz + t];
        sc[t] = s;
    }
    __syncthreads();

    // max reduce
    red[tid] = fmaxf(sc[tid], sc[tid + 256]);
    __syncthreads();
    for (int off = 128; off; off >>= 1) {
        if (tid < off) red[tid] = fmaxf(red[tid], red[tid + off]);
        __syncthreads();
    }
    const float m = red[0];
    __syncthreads();

    // exp + sum reduce
    float e0 = expf(sc[tid] - m);
    float e1 = expf(sc[tid + 256] - m);
    red[tid] = e0 + e1;
    __syncthreads();
    for (int off = 128; off; off >>= 1) {
        if (tid < off) red[tid] += red[tid + off];
        __syncthreads();
    }
    const float inv = 1.0f / red[0];
    sc[tid]       = e0 * inv;
    sc[tid + 256] = e1 * inv;
    __syncthreads();

    // weighted sum: out[b, d] = sum_t sc[t] * frames[b,t,d]
    const int d = blockIdx.x * 256 + tid;
    const float* fb = frames + (size_t)b * Tz * Dz + d;
    float a0 = 0.f, a1 = 0.f, a2 = 0.f, a3 = 0.f;
    float a4 = 0.f, a5 = 0.f, a6 = 0.f, a7 = 0.f;
    #pragma unroll 2
    for (int t = 0; t < Tz; t += 8) {
        a0 = fmaf(sc[t + 0], fb[(size_t)(t + 0) * Dz], a0);
        a1 = fmaf(sc[t + 1], fb[(size_t)(t + 1) * Dz], a1);
        a2 = fmaf(sc[t + 2], fb[(size_t)(t + 2) * Dz], a2);
        a3 = fmaf(sc[t + 3], fb[(size_t)(t + 3) * Dz], a3);
        a4 = fmaf(sc[t + 4], fb[(size_t)(t + 4) * Dz], a4);
        a5 = fmaf(sc[t + 5], fb[(size_t)(t + 5) * Dz], a5);
        a6 = fmaf(sc[t + 6], fb[(size_t)(t + 6) * Dz], a6);
        a7 = fmaf(sc[t + 7], fb[(size_t)(t + 7) * Dz], a7);
    }
    out[b * Dz + d] = ((a0 + a1) + (a2 + a3)) + ((a4 + a5) + (a6 + a7));
}

// ---------------------------------------------------------------------------
extern "C" void kernel_launch(void* const* d_in, const int* in_sizes, int n_in,
                              void* d_out, int out_size) {
    const float* frames = (const float*)d_in[0];
    const float* text   = (const float*)d_in[1];
    const float* Wa     = (const float*)d_in[2];
    const float* Ua     = (const float*)d_in[3];
    const float* Va     = (const float*)d_in[4];
    const float* ba     = (const float*)d_in[5];
    float* out          = (float*)d_out;

    float *uhp, *partial;
    __half* WaT;
    cudaGetSymbolAddress((void**)&uhp, g_uhp);
    cudaGetSymbolAddress((void**)&partial, g_partial);
    cudaGetSymbolAddress((void**)&WaT, g_WaT);

    cudaFuncSetAttribute(score_hmma_kernel,
                         cudaFuncAttributeMaxDynamicSharedMemorySize, SM_TOTAL);

    // 1) fused: Wa -> WaT (fp16 transpose)  ||  uh K-split partials
    prep_kernel<<<1024 + 2 * 8 * KSPL, 256>>>(Wa, text, Ua, ba, WaT, uhp);

    // 2) HMMA score GEMM + tanh·Va epilogue (partials per h-block)
    score_hmma_kernel<<<dim3(NBLK, BT / 128), 256, SM_TOTAL>>>(
        frames, WaT, uhp, Va, partial);

    // 3) fused softmax + weighted sum
    out_kernel<<<dim3(Dz / 256, Bz), 256>>>(partial, frames, out);
}

// round 15
// speedup vs baseline: 4.0257x; 1.0308x over previous
#include <cuda_runtime.h>
#include <cuda_fp16.h>
#include <math.h>
#include <cstdint>

// Problem dims (fixed per reference)
#define Bz 64
#define Tz 512
#define Dz 2048
#define Hz 512
#define BT (Bz * Tz)          // 32768
#define NBLK 4                // H/128 h-blocks for partial scores
#define KSPL 16               // uh K-splits

// Scratch (__device__ globals; allocation-free rule)
__device__ float g_uhp[KSPL * Bz * Hz];   // uh K-split partials
__device__ float g_partial[NBLK * BT];
__device__ __half g_WaT[Hz * Dz];         // Wa transposed -> [H, D] fp16

// ---------------------------------------------------------------------------
// helpers
// ---------------------------------------------------------------------------
__device__ __forceinline__ uint32_t smem_u32(const void* p) {
    uint32_t a;
    asm("{ .reg .u64 t; cvta.to.shared.u64 t, %1; cvt.u32.u64 %0, t; }"
        : "=r"(a) : "l"(p));
    return a;
}

#define SWZ(o) ((o) ^ (((o) >> 3) & 0x70))

__device__ __forceinline__ void ldsm4(uint32_t* a, uint32_t addr) {
    asm volatile("ldmatrix.sync.aligned.m8n8.x4.shared.b16 {%0,%1,%2,%3}, [%4];"
                 : "=r"(a[0]), "=r"(a[1]), "=r"(a[2]), "=r"(a[3]) : "r"(addr));
}
// fp16 inputs, fp32 accumulate
__device__ __forceinline__ void mma16816(float* c, const uint32_t* a,
                                         const uint32_t* b) {
    asm volatile(
        "mma.sync.aligned.m16n8k16.row.col.f32.f16.f16.f32 "
        "{%0,%1,%2,%3}, {%4,%5,%6,%7}, {%8,%9}, {%0,%1,%2,%3};"
        : "+f"(c[0]), "+f"(c[1]), "+f"(c[2]), "+f"(c[3])
        : "r"(a[0]), "r"(a[1]), "r"(a[2]), "r"(a[3]), "r"(b[0]), "r"(b[1]));
}
__device__ __forceinline__ float tanh_fast(float x) {
    float y;
    asm("tanh.approx.f32 %0, %1;" : "=f"(y) : "f"(x));
    return y;
}

// ---------------------------------------------------------------------------
// Kernel 1 (fused prep):
//   blocks [0,1024)      : WaT = fp16(Wa^T), 32x32 tile per block,
//                          one float4 LDG + 4 scalar STS + one 8B STG
//   blocks [1024,1280)   : uh partials, K-split 16 (128-wide slices):
//       uhp[ks][b][h] = sum_{d in slice} text[b,d]*Ua[d,h]  (+ba at ks=0)
// 256 threads per block; both jobs in one launch, fully parallel.
// ---------------------------------------------------------------------------
__global__ __launch_bounds__(256)
void prep_kernel(const float* __restrict__ Wa,
                 const float* __restrict__ text,
                 const float* __restrict__ Ua,
                 const float* __restrict__ ba,
                 __half* __restrict__ WaT,
                 float* __restrict__ uhp) {
    __shared__ float tile[32][33];      // transpose buffer (33-pad, scalar STS)
    __shared__ float ts[8][128];        // uh text slice (whole 128-K slice)
    const int tid = threadIdx.x;

    if (blockIdx.x < 1024) {
        // ---- transpose: 64 k-blocks x 16 n-blocks of 32x32 ----
        const int k0 = (blockIdx.x & 63) * 32;
        const int n0 = (blockIdx.x >> 6) * 32;
        const int row = tid >> 3;            // 0..31
        const int q   = tid & 7;             // 0..7 (float4 quad)
        // single-round load: tile[row][q*4..q*4+3] (scalar STS: 33-stride
        // rows are not 16B-aligned, float4 STS would trap)
        float4 v = *(const float4*)(Wa + (size_t)(k0 + row) * Hz + n0 + q * 4);
        tile[row][q * 4 + 0] = v.x;
        tile[row][q * 4 + 1] = v.y;
        tile[row][q * 4 + 2] = v.z;
        tile[row][q * 4 + 3] = v.w;
        __syncthreads();
        // write WaT row n=row, k-quad q: 4 halves (8B, aligned: Dz stride)
        __half h4[4];
        #pragma unroll
        for (int i = 0; i < 4; i++)
            h4[i] = __float2half_rn(tile[q * 4 + i][row]);
        *(uint2*)(WaT + (size_t)(n0 + row) * Dz + k0 + q * 4) = *(uint2*)h4;
    } else {
        // ---- uh partials: blk = hb(2) x bb(8) x ks(16) ----
        const int blk = blockIdx.x - 1024;       // 0..255
        const int hb = blk & 1;
        const int bb = (blk >> 1) & 7;
        const int ks = blk >> 4;
        const int h  = hb * 256 + tid;
        const int b0 = bb * 8;
        const int d_lo = ks * (Dz / KSPL);       // 128-wide K slice
        float acc[8] = {0.f, 0.f, 0.f, 0.f, 0.f, 0.f, 0.f, 0.f};

        // load the whole 8x128 text slice once (float4 per thread; aligned)
        {
            int i = tid >> 5, c4 = (tid & 31) * 4;
            *(float4*)&ts[i][c4] =
                *(const float4*)(text + (size_t)(b0 + i) * Dz + d_lo + c4);
        }
        __syncthreads();

        #pragma unroll 16
        for (int k = 0; k < Dz / KSPL; k++) {
            float u = Ua[(size_t)(d_lo + k) * Hz + h];
            #pragma unroll
            for (int i = 0; i < 8; i++) acc[i] = fmaf(ts[i][k], u, acc[i]);
        }
        const float bav = (ks == 0) ? ba[h] : 0.f;
        float* dst = uhp + (size_t)ks * (Bz * Hz);
        #pragma unroll
        for (int i = 0; i < 8; i++) dst[(b0 + i) * Hz + h] = acc[i] + bav;
    }
}

// ---------------------------------------------------------------------------
// Kernel 2: fp16 HMMA score GEMM (fp32 acc) + fused tanh·Va epilogue.
// CTA: M=128 rows (one b), N=128 h, 8 warps as 2(M) x 4(N), warp tile 64x32.
// K=2048 in 32 chunks of 64; triple-buffered smem, one sync per chunk.
// Epilogue sums the 16 uh K-split partials when loading uh.
// ---------------------------------------------------------------------------
#define ABUF(s) ((uint32_t)(s) * 16384u)            // 3 x 16KB
#define BBUF(s) (49152u + (uint32_t)(s) * 16384u)   // 3 x 16KB
#define SM_TOTAL 98304
#define NCHUNK 32

__global__ __launch_bounds__(256, 1)
void score_hmma_kernel(const float* __restrict__ frames,
                       const __half* __restrict__ WaT,
                       const float* __restrict__ uhp,
                       const float* __restrict__ Va,
                       float* __restrict__ partial) {
    extern __shared__ char smem[];
    const uint32_t sbase = smem_u32(smem);
    const int tid = threadIdx.x;
    const int wid = tid >> 5, lane = tid & 31;
    const int warp_m = wid & 1, warp_n = wid >> 1;    // 2 x 4
    const int wm = warp_m * 64, wn = warp_n * 32;
    const int h0   = blockIdx.x * 128;
    const int row0 = blockIdx.y * 128;

    float acc[4][4][4];
    #pragma unroll
    for (int i = 0; i < 4; i++)
        #pragma unroll
        for (int j = 0; j < 4; j++)
            #pragma unroll
            for (int e = 0; e < 4; e++) acc[i][j][e] = 0.f;

    float4 pa[8], pb[4];

    // global -> regs for chunk c
    auto loadG = [&](int c) {
        const float* fA = frames + (size_t)row0 * Dz + c * 64;
        #pragma unroll
        for (int v = 0; v < 8; v++) {
            int idx = tid + v * 256;          // 128 rows x 16 float4
            int r = idx >> 4, c4 = (idx & 15) << 2;
            pa[v] = *(const float4*)(fA + (size_t)r * Dz + c4);
        }
        const __half* fB = WaT + (size_t)h0 * Dz + c * 64;
        #pragma unroll
        for (int v = 0; v < 4; v++) {
            int idx = tid + v * 256;          // 128 rows x 8 x16B
            int n = idx >> 3, k8 = (idx & 7) << 3;
            pb[v] = *(const float4*)(fB + (size_t)n * Dz + k8);
        }
    };
    // regs -> smem buffer (A converted fp32 -> fp16)
    auto storeS = [&](uint32_t aoff, uint32_t boff) {
        #pragma unroll
        for (int v = 0; v < 8; v++) {
            int idx = tid + v * 256;
            int r = idx >> 4, c4 = (idx & 15) << 2;
            __half2 p0 = __float22half2_rn(make_float2(pa[v].x, pa[v].y));
            __half2 p1 = __float22half2_rn(make_float2(pa[v].z, pa[v].w));
            uint2 pk;
            pk.x = *(uint32_t*)&p0;
            pk.y = *(uint32_t*)&p1;
            *(uint2*)(smem + aoff + SWZ((uint32_t)(r * 128 + c4 * 2))) = pk;
        }
        #pragma unroll
        for (int v = 0; v < 4; v++) {
            int idx = tid + v * 256;
            int n = idx >> 3, k8 = (idx & 7) << 3;
            *(float4*)(smem + boff + SWZ((uint32_t)(n * 128 + k8 * 2))) = pb[v];
        }
    };
    // compute on buffer (aoff, boff): 4 k16-steps
    auto compute = [&](uint32_t aoff, uint32_t boff) {
        #pragma unroll
        for (int ks = 0; ks < 4; ks++) {
            const int k16 = ks * 16;
            uint32_t bfr[4][2];
            #pragma unroll
            for (int jj = 0; jj < 2; jj++) {
                uint32_t r4[4];
                int g = lane >> 3;
                uint32_t off = (uint32_t)((wn + jj * 16 + (g >> 1) * 8 + (lane & 7)) * 128 +
                                          (k16 + (g & 1) * 8) * 2);
                ldsm4(r4, sbase + boff + SWZ(off));
                bfr[jj * 2 + 0][0] = r4[0]; bfr[jj * 2 + 0][1] = r4[1];
                bfr[jj * 2 + 1][0] = r4[2]; bfr[jj * 2 + 1][1] = r4[3];
            }
            #pragma unroll
            for (int i = 0; i < 4; i++) {
                uint32_t afr[4];
                uint32_t off = (uint32_t)((wm + i * 16 + (lane & 15)) * 128 +
                                          (k16 + (lane >> 4) * 8) * 2);
                ldsm4(afr, sbase + aoff + SWZ(off));
                #pragma unroll
                for (int j = 0; j < 4; j++)
                    mma16816(acc[i][j], afr, bfr[j]);
            }
        }
    };

    // Prologue: chunk0 -> buf0; chunk1 staged in regs
    loadG(0);
    storeS(ABUF(0), BBUF(0));
    loadG(1);

    for (int i = 0; i < NCHUNK; i++) {
        __syncthreads();   // all warps done computing chunk i-1; STS of chunk i visible
        if (i + 1 < NCHUNK) {
            const int s = (i + 1) % 3;
            storeS(ABUF(s), BBUF(s));          // regs hold chunk i+1
        }
        if (i + 2 < NCHUNK) loadG(i + 2);       // issue LDGs; land during compute
        const int s = i % 3;
        compute(ABUF(s), BBUF(s));
    }

    // ---- epilogue: tanh + Va-weighted sum over this CTA's 128 h-cols ----
    const int b = row0 >> 9;
    float va_r[8], uh_r[8];
    #pragma unroll
    for (int j = 0; j < 4; j++) {
        int col = h0 + wn + j * 8 + (lane & 3) * 2;
        va_r[j * 2 + 0] = __ldg(Va + col);
        va_r[j * 2 + 1] = __ldg(Va + col + 1);
        float u0 = 0.f, u1 = 0.f;
        #pragma unroll
        for (int p = 0; p < KSPL; p++) {
            const float* up = uhp + (size_t)p * (Bz * Hz) + b * Hz + col;
            u0 += __ldg(up);
            u1 += __ldg(up + 1);
        }
        uh_r[j * 2 + 0] = u0;
        uh_r[j * 2 + 1] = u1;
    }
    __syncthreads();
    float* red = (float*)smem;    // [128][4] overlay

    #pragma unroll
    for (int i = 0; i < 4; i++) {
        float s0 = 0.f, s1 = 0.f;
        #pragma unroll
        for (int j = 0; j < 4; j++) {
            s0 = fmaf(va_r[j*2+0], tanh_fast(acc[i][j][0] + uh_r[j*2+0]), s0);
            s0 = fmaf(va_r[j*2+1], tanh_fast(acc[i][j][1] + uh_r[j*2+1]), s0);
            s1 = fmaf(va_r[j*2+0], tanh_fast(acc[i][j][2] + uh_r[j*2+0]), s1);
            s1 = fmaf(va_r[j*2+1], tanh_fast(acc[i][j][3] + uh_r[j*2+1]), s1);
        }
        s0 += __shfl_xor_sync(0xffffffffu, s0, 1);
        s0 += __shfl_xor_sync(0xffffffffu, s0, 2);
        s1 += __shfl_xor_sync(0xffffffffu, s1, 1);
        s1 += __shfl_xor_sync(0xffffffffu, s1, 2);
        if ((lane & 3) == 0) {
            int r = wm + i * 16 + (lane >> 2);
            red[r * 4 + warp_n] = s0;
            red[(r + 8) * 4 + warp_n] = s1;
        }
    }
    __syncthreads();
    if (tid < 128) {
        float s = red[tid * 4] + red[tid * 4 + 1] +
                  red[tid * 4 + 2] + red[tid * 4 + 3];
        partial[(size_t)blockIdx.x * BT + row0 + tid] = s;
    }
}

// ---------------------------------------------------------------------------
// Kernel 3 (fused): per-CTA softmax recompute (from score partials, cheap)
// + weighted sum over frames. grid (8, B): CTA = (d-block of 256, batch b).
// ---------------------------------------------------------------------------
__global__ __launch_bounds__(256)
void out_kernel(const float* __restrict__ partial,
                const float* __restrict__ frames,
                float* __restrict__ out) {
    const int b = blockIdx.y;
    const int tid = threadIdx.x;

    __shared__ float sc[Tz];
    __shared__ float red[256];

    // scores for this b (sum of NBLK h-block partials)
    #pragma unroll
    for (int t = tid; t < Tz; t += 256) {
        float s = 0.f;
        #pragma unroll
        for (int p = 0; p < NBLK; p++)
            s += partial[(size_t)p * BT + b * Tz + t];
        sc[t] = s;
    }
    __syncthreads();

    // max reduce
    red[tid] = fmaxf(sc[tid], sc[tid + 256]);
    __syncthreads();
    for (int off = 128; off; off >>= 1) {
        if (tid < off) red[tid] = fmaxf(red[tid], red[tid + off]);
        __syncthreads();
    }
    const float m = red[0];
    __syncthreads();

    // exp + sum reduce
    float e0 = expf(sc[tid] - m);
    float e1 = expf(sc[tid + 256] - m);
    red[tid] = e0 + e1;
    __syncthreads();
    for (int off = 128; off; off >>= 1) {
        if (tid < off) red[tid] += red[tid + off];
        __syncthreads();
    }
    const float inv = 1.0f / red[0];
    sc[tid]       = e0 * inv;
    sc[tid + 256] = e1 * inv;
    __syncthreads();

    // weighted sum: out[b, d] = sum_t sc[t] * frames[b,t,d]
    const int d = blockIdx.x * 256 + tid;
    const float* fb = frames + (size_t)b * Tz * Dz + d;
    float a0 = 0.f, a1 = 0.f, a2 = 0.f, a3 = 0.f;
    float a4 = 0.f, a5 = 0.f, a6 = 0.f, a7 = 0.f;
    #pragma unroll 2
    for (int t = 0; t < Tz; t += 8) {
        a0 = fmaf(sc[t + 0], fb[(size_t)(t + 0) * Dz], a0);
        a1 = fmaf(sc[t + 1], fb[(size_t)(t + 1) * Dz], a1);
        a2 = fmaf(sc[t + 2], fb[(size_t)(t + 2) * Dz], a2);
        a3 = fmaf(sc[t + 3], fb[(size_t)(t + 3) * Dz], a3);
        a4 = fmaf(sc[t + 4], fb[(size_t)(t + 4) * Dz], a4);
        a5 = fmaf(sc[t + 5], fb[(size_t)(t + 5) * Dz], a5);
        a6 = fmaf(sc[t + 6], fb[(size_t)(t + 6) * Dz], a6);
        a7 = fmaf(sc[t + 7], fb[(size_t)(t + 7) * Dz], a7);
    }
    out[b * Dz + d] = ((a0 + a1) + (a2 + a3)) + ((a4 + a5) + (a6 + a7));
}

// ---------------------------------------------------------------------------
extern "C" void kernel_launch(void* const* d_in, const int* in_sizes, int n_in,
                              void* d_out, int out_size) {
    const float* frames = (const float*)d_in[0];
    const float* text   = (const float*)d_in[1];
    const float* Wa     = (const float*)d_in[2];
    const float* Ua     = (const float*)d_in[3];
    const float* Va     = (const float*)d_in[4];
    const float* ba     = (const float*)d_in[5];
    float* out          = (float*)d_out;

    float *uhp, *partial;
    __half* WaT;
    cudaGetSymbolAddress((void**)&uhp, g_uhp);
    cudaGetSymbolAddress((void**)&partial, g_partial);
    cudaGetSymbolAddress((void**)&WaT, g_WaT);

    cudaFuncSetAttribute(score_hmma_kernel,
                         cudaFuncAttributeMaxDynamicSharedMemorySize, SM_TOTAL);

    // 1) fused: Wa -> WaT (fp16 transpose)  ||  uh K-split partials
    prep_kernel<<<1024 + 2 * 8 * KSPL, 256>>>(Wa, text, Ua, ba, WaT, uhp);

    // 2) HMMA score GEMM + tanh·Va epilogue (partials per h-block)
    score_hmma_kernel<<<dim3(NBLK, BT / 128), 256, SM_TOTAL>>>(
        frames, WaT, uhp, Va, partial);

    // 3) fused softmax + weighted sum
    out_kernel<<<dim3(Dz / 256, Bz), 256>>>(partial, frames, out);
}